// round 11
// baseline (speedup 1.0000x reference)
#include <cuda_runtime.h>
#include <cuda_fp16.h>
#include <math.h>

// Problem constants (fixed by the dataset)
#define NB 256      // batch (docs)
#define NL 512      // tokens per doc
#define ND 1024     // embedding dim
#define NV 50001    // emb_table rows
// emb_table is (V+1, D) = (50001, 1024) float32

// Scratch (device globals — no allocation allowed)
__device__ float g_hpart[NB * 2 * ND];   // per-doc 2-way partial sums (fp32 gather)
__device__ float g_v[NB * ND];           // v[b] = W_b @ mean(emb[b])
__device__ uint2 g_ef[(size_t)NV * 256]; // fp16 table: 2048 B/row (256 uint2)

__device__ __forceinline__ unsigned h2_bits(__half2 h) {
    unsigned u;
    memcpy(&u, &h, 4);
    return u;
}
__device__ __forceinline__ float4 u2_to_f4(uint2 q) {
    __half2 h01, h23;
    memcpy(&h01, &q.x, 4);
    memcpy(&h23, &q.y, 4);
    float2 a = __half22float2(h01);
    float2 b = __half22float2(h23);
    return make_float4(a.x, a.y, b.x, b.y);
}

#define GATHER_CTAS 512
#define CONV_CTAS   1536

// ---------------------------------------------------------------------------
// Merged kernel: fp32 gather partial-sums (CTAs 0..511) + fp32->fp16 table
// convert (CTAs 512..2047). Both read the SAME fp32 table, so their DRAM
// reads dedup in L2: ~205 MB unique read + 102 MB write instead of ~390+102
// serial. Gather keeps fp32 precision for hidden.
// ---------------------------------------------------------------------------
__global__ void k_gather_convert(const int* __restrict__ tokens,
                                 const float* __restrict__ emb) {
    if (blockIdx.x < GATHER_CTAS) {
        // ---- gather: 2 CTAs per doc, 256 tokens each, float4 per thread ----
        __shared__ int s_tok[256];
        const int b    = blockIdx.x >> 1;
        const int part = blockIdx.x & 1;
        const int t    = threadIdx.x;

        s_tok[t] = tokens[b * NL + part * 256 + t] + 1;
        __syncthreads();

        const float4* emb4 = reinterpret_cast<const float4*>(emb);
        float4 acc = make_float4(0.f, 0.f, 0.f, 0.f);

#pragma unroll 4
        for (int l = 0; l < 256; ++l) {
            const int row = s_tok[l];
            float4 e = __ldg(&emb4[(size_t)row * 256 + t]);
            acc.x += e.x; acc.y += e.y; acc.z += e.z; acc.w += e.w;
        }
        reinterpret_cast<float4*>(g_hpart)[(b * 2 + part) * 256 + t] = acc;
    } else {
        // ---- convert: grid-stride fp32 -> fp16 over the whole table ----
        const float4* src = reinterpret_cast<const float4*>(emb);
        const size_t n = (size_t)NV * 256;
        size_t i = (size_t)(blockIdx.x - GATHER_CTAS) * blockDim.x + threadIdx.x;
        const size_t stride = (size_t)CONV_CTAS * blockDim.x;
        for (; i < n; i += stride) {
            float4 v = __ldg(&src[i]);
            uint2 o;
            o.x = h2_bits(__floats2half2_rn(v.x, v.y));
            o.y = h2_bits(__floats2half2_rn(v.z, v.w));
            g_ef[i] = o;
        }
    }
}

// ---------------------------------------------------------------------------
// Small GEMM (R1 scalar): v[b,n] = sum_e hidden[b,e] * W[n,e],
// hidden = (p0+p1)/512. M=256, N=1024, K=1024. BM=32, BN=64, BK=32.
// ---------------------------------------------------------------------------
__global__ void k_v(const float* __restrict__ W) {
    __shared__ float sA[32 * 34];   // [k][m], pad to 34
    __shared__ float sB[32 * 68];   // [k][n], pad to 68

    const int tid = threadIdx.x;
    const int bn0 = blockIdx.x * 64;
    const int bm0 = blockIdx.y * 32;
    const int tx  = tid & 15;
    const int ty  = tid >> 4;
    const int lm  = tid >> 3;
    const int lk  = tid & 7;

    const float4* W4  = reinterpret_cast<const float4*>(W);
    const float4* hp4 = reinterpret_cast<const float4*>(g_hpart);

    float acc[2][4] = {{0.f,0.f,0.f,0.f},{0.f,0.f,0.f,0.f}};

    for (int k0 = 0; k0 < 1024; k0 += 32) {
        {
            const int bb = bm0 + lm;
            float4 h0 = hp4[bb * 512 +       (k0 >> 2) + lk];
            float4 h1 = hp4[bb * 512 + 256 + (k0 >> 2) + lk];
            const float s = 1.0f / 512.0f;
            sA[(lk * 4 + 0) * 34 + lm] = (h0.x + h1.x) * s;
            sA[(lk * 4 + 1) * 34 + lm] = (h0.y + h1.y) * s;
            sA[(lk * 4 + 2) * 34 + lm] = (h0.z + h1.z) * s;
            sA[(lk * 4 + 3) * 34 + lm] = (h0.w + h1.w) * s;
        }
#pragma unroll
        for (int r = 0; r < 2; ++r) {
            const int n = lm + r * 32;
            float4 w = W4[(size_t)(bn0 + n) * 256 + (k0 >> 2) + lk];
            sB[(lk * 4 + 0) * 68 + n] = w.x;
            sB[(lk * 4 + 1) * 68 + n] = w.y;
            sB[(lk * 4 + 2) * 68 + n] = w.z;
            sB[(lk * 4 + 3) * 68 + n] = w.w;
        }
        __syncthreads();

#pragma unroll
        for (int k = 0; k < 32; ++k) {
            float2 a2 = *reinterpret_cast<const float2*>(&sA[k * 34 + ty * 2]);
            float4 b4 = *reinterpret_cast<const float4*>(&sB[k * 68 + tx * 4]);
            acc[0][0] += a2.x * b4.x; acc[0][1] += a2.x * b4.y;
            acc[0][2] += a2.x * b4.z; acc[0][3] += a2.x * b4.w;
            acc[1][0] += a2.y * b4.x; acc[1][1] += a2.y * b4.y;
            acc[1][2] += a2.y * b4.z; acc[1][3] += a2.y * b4.w;
        }
        __syncthreads();
    }

#pragma unroll
    for (int i = 0; i < 2; ++i) {
        const int row = bm0 + ty * 2 + i;
        float4 o = make_float4(acc[i][0], acc[i][1], acc[i][2], acc[i][3]);
        reinterpret_cast<float4*>(g_v)[row * 256 + (bn0 >> 2) + tx] = o;
    }
}

// ---------------------------------------------------------------------------
// Pass 2: split-D warp pairs reading the fp16 table (EXACT R9 version, 53us).
// 1 CTA/doc, 512 thr = 8 pairs; pair p: tokens p*64..+63, half h owns
// D-components h*512..+511 (4 uint2 loads -> 4 float4 per lane per token).
// 2 CTAs/SM -> 256 CTAs in one wave, 32 warps/SM.
// ---------------------------------------------------------------------------
__global__ void __launch_bounds__(512, 2)
k_ct(const int* __restrict__ tokens, float* __restrict__ out) {
    __shared__ int   s_tok[512];
    __shared__ float s_ct[1024];
    __shared__ float s_ex[8][2][2];   // [pair][token parity][half]
    __shared__ float s_m[8];
    __shared__ float s_d[8];

    const int b    = blockIdx.x;
    const int tid  = threadIdx.x;
    const int w    = tid >> 5;
    const int p    = w >> 1;          // pair 0..7
    const int h    = w & 1;           // D-half 0/1
    const int lane = tid & 31;

    s_tok[tid]      = tokens[b * NL + tid] + 1;
    s_ct[tid]       = 0.f;
    s_ct[tid + 512] = 0.f;
    __syncthreads();

    const float4* v4   = reinterpret_cast<const float4*>(g_v);
    const uint2*  base = g_ef + h * 128 + lane;   // half-row base + lane offset

    // lane owns D-components d = h*512 + it*128 + lane*4 .. +3, it = 0..3
    float4 vr[4];
#pragma unroll
    for (int it = 0; it < 4; ++it) vr[it] = v4[b * 256 + h * 128 + it * 32 + lane];

    float4 nacc[4];
#pragma unroll
    for (int it = 0; it < 4; ++it) nacc[it] = make_float4(0.f, 0.f, 0.f, 0.f);

    float m   = -INFINITY;
    float den = 0.f;

    for (int j = 0; j < 64; ++j) {
        const int row = s_tok[p * 64 + j];
        const uint2* q = base + (size_t)row * 256;

        // 4 independent LDG.64 (fp16), convert on arrival
        uint2 raw[4];
#pragma unroll
        for (int it = 0; it < 4; ++it) raw[it] = __ldg(&q[it * 32]);

        float4 e[4];
        float  s = 0.f;
#pragma unroll
        for (int it = 0; it < 4; ++it) {
            e[it] = u2_to_f4(raw[it]);
            s += e[it].x * vr[it].x + e[it].y * vr[it].y
               + e[it].z * vr[it].z + e[it].w * vr[it].w;
        }
#pragma unroll
        for (int o = 16; o; o >>= 1) s += __shfl_xor_sync(0xffffffffu, s, o);

        if (lane == 0) s_ex[p][j & 1][h] = s;
        asm volatile("bar.sync %0, 64;" :: "r"(p + 1) : "memory");
        s = s_ex[p][j & 1][0] + s_ex[p][j & 1][1];

        const float m_new = fmaxf(m, s);
        const float c  = __expf(m - m_new);   // 1 when max unchanged, 0 on first
        const float wl = __expf(s - m_new);
        den = den * c + wl;
        if (c != 1.0f) {
#pragma unroll
            for (int it = 0; it < 4; ++it) {
                nacc[it].x *= c; nacc[it].y *= c;
                nacc[it].z *= c; nacc[it].w *= c;
            }
        }
#pragma unroll
        for (int it = 0; it < 4; ++it) {
            nacc[it].x += wl * e[it].x; nacc[it].y += wl * e[it].y;
            nacc[it].z += wl * e[it].z; nacc[it].w += wl * e[it].w;
        }
        m = m_new;
    }

    // per-pair state (identical in both halves of a pair)
    if (h == 0 && lane == 0) { s_m[p] = m; s_d[p] = den; }
    __syncthreads();

    float M = -INFINITY;
#pragma unroll
    for (int i = 0; i < 8; ++i) M = fmaxf(M, s_m[i]);
    float dg = 0.f;
#pragma unroll
    for (int i = 0; i < 8; ++i) dg += s_d[i] * __expf(s_m[i] - M);

    const float sc = __expf(m - M) / dg;
#pragma unroll
    for (int it = 0; it < 4; ++it) {
        const int d0 = h * 512 + it * 128 + lane * 4;
        atomicAdd(&s_ct[d0 + 0], nacc[it].x * sc);
        atomicAdd(&s_ct[d0 + 1], nacc[it].y * sc);
        atomicAdd(&s_ct[d0 + 2], nacc[it].z * sc);
        atomicAdd(&s_ct[d0 + 3], nacc[it].w * sc);
    }
    __syncthreads();

    out[b * ND + tid]       = s_ct[tid];
    out[b * ND + tid + 512] = s_ct[tid + 512];
}

// ---------------------------------------------------------------------------
extern "C" void kernel_launch(void* const* d_in, const int* in_sizes, int n_in,
                              void* d_out, int out_size) {
    const int*   tokens = (const int*)d_in[0];
    // d_in[1] = max_len (scalar, unused — fixed at 512)
    const float* emb    = (const float*)d_in[2];
    const float* W      = (const float*)d_in[3];
    float*       out    = (float*)d_out;

    k_gather_convert<<<GATHER_CTAS + CONV_CTAS, 256>>>(tokens, emb);
    k_v<<<dim3(16, 8), 256>>>(W);
    k_ct<<<NB, 512>>>(tokens, out);
}

// round 12
// speedup vs baseline: 1.1536x; 1.1536x over previous
#include <cuda_runtime.h>
#include <math.h>

// Problem constants (fixed by the dataset)
#define NB 256      // batch (docs)
#define NL 512      // tokens per doc
#define ND 1024     // embedding dim
// emb_table is (V+1, D) = (50001, 1024) float32

#define STAGES 3
#define ROW_BYTES 4096

// Scratch (device globals — no allocation allowed)
__device__ float g_hpart[NB * 2 * ND];  // per-doc 2-way partial sums of emb rows
__device__ float g_v[NB * ND];          // v[b] = W_b @ mean(emb[b])

// ---------------------------------------------------------------------------
// helpers
// ---------------------------------------------------------------------------
__device__ __forceinline__ unsigned smem_u32(const void* p) {
    unsigned a;
    asm("{ .reg .u64 t; cvta.to.shared.u64 t, %1; cvt.u32.u64 %0, t; }"
        : "=r"(a) : "l"(p));
    return a;
}
__device__ __forceinline__ void mbar_init(unsigned mbar, unsigned count) {
    asm volatile("mbarrier.init.shared.b64 [%0], %1;" :: "r"(mbar), "r"(count)
                 : "memory");
}
__device__ __forceinline__ void mbar_expect_tx(unsigned mbar, unsigned bytes) {
    asm volatile("mbarrier.arrive.expect_tx.shared.b64 _, [%0], %1;"
                 :: "r"(mbar), "r"(bytes) : "memory");
}
__device__ __forceinline__ void mbar_arrive(unsigned mbar) {
    asm volatile("mbarrier.arrive.shared.b64 _, [%0];" :: "r"(mbar) : "memory");
}
__device__ __forceinline__ void mbar_wait(unsigned mbar, unsigned ph) {
    asm volatile(
        "{\n\t.reg .pred P;\n\t"
        "W_%=:\n\t"
        "mbarrier.try_wait.parity.acquire.cta.shared::cta.b64 P, [%0], %1, 0x989680;\n\t"
        "@!P bra W_%=;\n\t}"
        :: "r"(mbar), "r"(ph) : "memory");
}
__device__ __forceinline__ void bulk_ld(unsigned dst_smem, const void* src,
                                        unsigned mbar) {
    asm volatile(
        "cp.async.bulk.shared::cluster.global.mbarrier::complete_tx::bytes "
        "[%0], [%1], %2, [%3];"
        :: "r"(dst_smem), "l"(src), "r"((unsigned)ROW_BYTES), "r"(mbar)
        : "memory");
}

// ---------------------------------------------------------------------------
// Pass 1: partial sums of gathered embedding rows.  (EXACT R6/R1 version)
// ---------------------------------------------------------------------------
__global__ void k_hidden(const int* __restrict__ tokens,
                         const float* __restrict__ emb) {
    __shared__ int s_tok[256];
    const int b    = blockIdx.x >> 1;
    const int part = blockIdx.x & 1;
    const int t    = threadIdx.x;

    s_tok[t] = tokens[b * NL + part * 256 + t] + 1;   // +1 per reference lookup
    __syncthreads();

    const float4* emb4 = reinterpret_cast<const float4*>(emb);
    float4 acc = make_float4(0.f, 0.f, 0.f, 0.f);

#pragma unroll 4
    for (int l = 0; l < 256; ++l) {
        const int row = s_tok[l];
        float4 e = __ldg(&emb4[(size_t)row * 256 + t]);
        acc.x += e.x; acc.y += e.y; acc.z += e.z; acc.w += e.w;
    }
    reinterpret_cast<float4*>(g_hpart)[(b * 2 + part) * 256 + t] = acc;
}

// ---------------------------------------------------------------------------
// Small GEMM (R1 scalar): v[b,n] = sum_e hidden[b,e] * W[n,e].
// ---------------------------------------------------------------------------
__global__ void k_v(const float* __restrict__ W) {
    __shared__ float sA[32 * 34];   // [k][m], pad to 34
    __shared__ float sB[32 * 68];   // [k][n], pad to 68

    const int tid = threadIdx.x;
    const int bn0 = blockIdx.x * 64;
    const int bm0 = blockIdx.y * 32;
    const int tx  = tid & 15;
    const int ty  = tid >> 4;
    const int lm  = tid >> 3;
    const int lk  = tid & 7;

    const float4* W4  = reinterpret_cast<const float4*>(W);
    const float4* hp4 = reinterpret_cast<const float4*>(g_hpart);

    float acc[2][4] = {{0.f,0.f,0.f,0.f},{0.f,0.f,0.f,0.f}};

    for (int k0 = 0; k0 < 1024; k0 += 32) {
        {
            const int bb = bm0 + lm;
            float4 h0 = hp4[bb * 512 +       (k0 >> 2) + lk];
            float4 h1 = hp4[bb * 512 + 256 + (k0 >> 2) + lk];
            const float s = 1.0f / 512.0f;
            sA[(lk * 4 + 0) * 34 + lm] = (h0.x + h1.x) * s;
            sA[(lk * 4 + 1) * 34 + lm] = (h0.y + h1.y) * s;
            sA[(lk * 4 + 2) * 34 + lm] = (h0.z + h1.z) * s;
            sA[(lk * 4 + 3) * 34 + lm] = (h0.w + h1.w) * s;
        }
#pragma unroll
        for (int r = 0; r < 2; ++r) {
            const int n = lm + r * 32;
            float4 w = W4[(size_t)(bn0 + n) * 256 + (k0 >> 2) + lk];
            sB[(lk * 4 + 0) * 68 + n] = w.x;
            sB[(lk * 4 + 1) * 68 + n] = w.y;
            sB[(lk * 4 + 2) * 68 + n] = w.z;
            sB[(lk * 4 + 3) * 68 + n] = w.w;
        }
        __syncthreads();

#pragma unroll
        for (int k = 0; k < 32; ++k) {
            float2 a2 = *reinterpret_cast<const float2*>(&sA[k * 34 + ty * 2]);
            float4 b4 = *reinterpret_cast<const float4*>(&sB[k * 68 + tx * 4]);
            acc[0][0] += a2.x * b4.x; acc[0][1] += a2.x * b4.y;
            acc[0][2] += a2.x * b4.z; acc[0][3] += a2.x * b4.w;
            acc[1][0] += a2.y * b4.x; acc[1][1] += a2.y * b4.y;
            acc[1][2] += a2.y * b4.z; acc[1][3] += a2.y * b4.w;
        }
        __syncthreads();
    }

#pragma unroll
    for (int i = 0; i < 2; ++i) {
        const int row = bm0 + ty * 2 + i;
        float4 o = make_float4(acc[i][0], acc[i][1], acc[i][2], acc[i][3]);
        reinterpret_cast<float4*>(g_v)[row * 256 + (bn0 >> 2) + tx] = o;
    }
}

// ---------------------------------------------------------------------------
// Pass 2: split-D warp pairs; rows fetched by cp.async.bulk into a per-pair
// smem ring (3 stages x 4KB), consumed via LDS. 1 CTA/doc, 512 thr = 8 pairs.
// Producer = thread 0 of each pair. 2 CTAs/SM -> one wave.
// Dynamic smem: ring[8][STAGES][1024] floats = 96 KB.
// ---------------------------------------------------------------------------
__global__ void __launch_bounds__(512, 2)
k_ct(const int* __restrict__ tokens, const float* __restrict__ emb,
     float* __restrict__ out) {
    extern __shared__ float ring[];   // [8][STAGES][1024]
    __shared__ int   s_tok[512];
    __shared__ float s_ct[1024];
    __shared__ float s_ex[8][2][2];   // [pair][token parity][half]
    __shared__ float s_m[8];
    __shared__ float s_d[8];
    __shared__ unsigned long long s_full[8][STAGES];
    __shared__ unsigned long long s_empty[8][STAGES];

    const int b    = blockIdx.x;
    const int tid  = threadIdx.x;
    const int w    = tid >> 5;
    const int p    = w >> 1;          // pair 0..7
    const int h    = w & 1;           // D-half 0/1
    const int lane = tid & 31;
    const int pt   = tid & 63;        // thread within pair

    s_tok[tid]      = tokens[b * NL + tid] + 1;
    s_ct[tid]       = 0.f;
    s_ct[tid + 512] = 0.f;
    if (tid < 8 * STAGES) {
        mbar_init(smem_u32(&s_full[tid / STAGES][tid % STAGES]), 1);
    } else if (tid < 16 * STAGES) {
        const int t2 = tid - 8 * STAGES;
        mbar_init(smem_u32(&s_empty[t2 / STAGES][t2 % STAGES]), 64);
    }
    __syncthreads();

    const unsigned ring_base = smem_u32(ring);
    const unsigned fullb  = smem_u32(&s_full[p][0]);
    const unsigned emptyb = smem_u32(&s_empty[p][0]);
    const float*   pair_ring = ring + p * (STAGES * 1024);

    const float4* v4 = reinterpret_cast<const float4*>(g_v);

    // lane owns D-components d = h*512 + it*128 + lane*4 .. +3, it = 0..3
    float4 vr[4];
#pragma unroll
    for (int it = 0; it < 4; ++it) vr[it] = v4[b * 256 + h * 128 + it * 32 + lane];

    float4 nacc[4];
#pragma unroll
    for (int it = 0; it < 4; ++it) nacc[it] = make_float4(0.f, 0.f, 0.f, 0.f);

    float m   = -INFINITY;
    float den = 0.f;

    // Prologue: producer fills all STAGES
    if (pt == 0) {
#pragma unroll
        for (int s = 0; s < STAGES; ++s) {
            const int row = s_tok[p * 64 + s];
            mbar_expect_tx(fullb + s * 8, ROW_BYTES);
            bulk_ld(ring_base + (unsigned)((p * STAGES + s) << 12),
                    emb + (size_t)row * ND, fullb + s * 8);
        }
    }

    int st = 0, ph = 0;
    for (int j = 0; j < 64; ++j) {
        mbar_wait(fullb + st * 8, ph);

        // read this half's 2KB from the stage buffer (LDS.128, conflict-free)
        const float4* rs =
            reinterpret_cast<const float4*>(pair_ring + st * 1024 + h * 512) + lane;
        float4 e[4];
        e[0] = rs[0]; e[1] = rs[32]; e[2] = rs[64]; e[3] = rs[96];

        float s = 0.f;
#pragma unroll
        for (int it = 0; it < 4; ++it)
            s += e[it].x * vr[it].x + e[it].y * vr[it].y
               + e[it].z * vr[it].z + e[it].w * vr[it].w;

        // row is in registers; release the stage
        mbar_arrive(emptyb + st * 8);

        // producer: refill this stage with row j+STAGES once both warps drained
        if (pt == 0 && j + STAGES < 64) {
            mbar_wait(emptyb + st * 8, ph);
            const int row = s_tok[p * 64 + j + STAGES];
            mbar_expect_tx(fullb + st * 8, ROW_BYTES);
            bulk_ld(ring_base + (unsigned)((p * STAGES + st) << 12),
                    emb + (size_t)row * ND, fullb + st * 8);
        }

#pragma unroll
        for (int o = 16; o; o >>= 1) s += __shfl_xor_sync(0xffffffffu, s, o);

        if (lane == 0) s_ex[p][j & 1][h] = s;
        asm volatile("bar.sync %0, 64;" :: "r"(p + 1) : "memory");
        s = s_ex[p][j & 1][0] + s_ex[p][j & 1][1];

        const float m_new = fmaxf(m, s);
        const float c  = __expf(m - m_new);   // 1 when max unchanged, 0 on first
        const float wl = __expf(s - m_new);
        den = den * c + wl;
        if (c != 1.0f) {
#pragma unroll
            for (int it = 0; it < 4; ++it) {
                nacc[it].x *= c; nacc[it].y *= c;
                nacc[it].z *= c; nacc[it].w *= c;
            }
        }
#pragma unroll
        for (int it = 0; it < 4; ++it) {
            nacc[it].x += wl * e[it].x; nacc[it].y += wl * e[it].y;
            nacc[it].z += wl * e[it].z; nacc[it].w += wl * e[it].w;
        }
        m = m_new;

        if (++st == STAGES) { st = 0; ph ^= 1; }
    }

    // per-pair state (identical in both halves of a pair)
    if (h == 0 && lane == 0) { s_m[p] = m; s_d[p] = den; }
    __syncthreads();

    float M = -INFINITY;
#pragma unroll
    for (int i = 0; i < 8; ++i) M = fmaxf(M, s_m[i]);
    float dg = 0.f;
#pragma unroll
    for (int i = 0; i < 8; ++i) dg += s_d[i] * __expf(s_m[i] - M);

    const float sc = __expf(m - M) / dg;
#pragma unroll
    for (int it = 0; it < 4; ++it) {
        const int d0 = h * 512 + it * 128 + lane * 4;
        atomicAdd(&s_ct[d0 + 0], nacc[it].x * sc);
        atomicAdd(&s_ct[d0 + 1], nacc[it].y * sc);
        atomicAdd(&s_ct[d0 + 2], nacc[it].z * sc);
        atomicAdd(&s_ct[d0 + 3], nacc[it].w * sc);
    }
    __syncthreads();

    out[b * ND + tid]       = s_ct[tid];
    out[b * ND + tid + 512] = s_ct[tid + 512];
}

// ---------------------------------------------------------------------------
extern "C" void kernel_launch(void* const* d_in, const int* in_sizes, int n_in,
                              void* d_out, int out_size) {
    const int*   tokens = (const int*)d_in[0];
    // d_in[1] = max_len (scalar, unused — fixed at 512)
    const float* emb    = (const float*)d_in[2];
    const float* W      = (const float*)d_in[3];
    float*       out    = (float*)d_out;

    const int ring_bytes = 8 * STAGES * 1024 * (int)sizeof(float);  // 96 KB
    cudaFuncSetAttribute(k_ct, cudaFuncAttributeMaxDynamicSharedMemorySize,
                         ring_bytes);

    k_hidden<<<NB * 2, 256>>>(tokens, emb);
    k_v<<<dim3(16, 8), 256>>>(W);
    k_ct<<<NB, 512, ring_bytes>>>(tokens, emb, out);
}